// round 1
// baseline (speedup 1.0000x reference)
#include <cuda_runtime.h>

#define BB  4
#define CC  256
#define CQK 32
#define NN  4096

// Scratch (allocation-free: __device__ globals)
__device__ float g_q[BB * CQK * NN];                 // 2 MB
__device__ float g_k[BB * CQK * NN];                 // 2 MB
__device__ float g_v[BB * CC * NN];                  // 16 MB
__device__ float g_s[(size_t)BB * NN * NN];          // 256 MB scores/attn

// ---------------------------------------------------------------------------
// 1) Projection: y[b, o, n] = sum_c W[o,c] * x[b,c,n] + bias[o]
//    which: 0 -> g_q, 1 -> g_k, 2 -> g_v.  O = number of output channels.
//    grid: (NN/1024, O/16, BB), block 256. Each thread: 16 o x 4 n.
// ---------------------------------------------------------------------------
__global__ void proj_kernel(const float* __restrict__ x,
                            const float* __restrict__ W,
                            const float* __restrict__ bias,
                            int which, int O) {
    __shared__ float sW[CC][16];   // [c][o] so compute reads are float4 broadcasts
    __shared__ float sb[16];

    const int b   = blockIdx.z;
    const int o0  = blockIdx.y * 16;
    const int tid = threadIdx.x;

    float* y = (which == 0) ? g_q : (which == 1) ? g_k : g_v;

#pragma unroll
    for (int i = 0; i < 16; i++) {
        int idx = tid + i * 256;
        int o = idx >> 8;        // 0..15
        int c = idx & 255;       // coalesced global read along c
        sW[c][o] = W[(o0 + o) * CC + c];
    }
    if (tid < 16) sb[tid] = bias[o0 + tid];
    __syncthreads();

    const int n0 = blockIdx.x * 1024 + tid * 4;
    float acc[16][4];
#pragma unroll
    for (int o = 0; o < 16; o++)
#pragma unroll
        for (int j = 0; j < 4; j++) acc[o][j] = 0.f;

    const float* xp = x + (size_t)b * CC * NN + n0;

#pragma unroll 4
    for (int c = 0; c < CC; c++) {
        float4 xv = *(const float4*)(xp + (size_t)c * NN);
        float4 w0 = *(const float4*)&sW[c][0];
        float4 w1 = *(const float4*)&sW[c][4];
        float4 w2 = *(const float4*)&sW[c][8];
        float4 w3 = *(const float4*)&sW[c][12];
        float wv[16] = {w0.x, w0.y, w0.z, w0.w, w1.x, w1.y, w1.z, w1.w,
                        w2.x, w2.y, w2.z, w2.w, w3.x, w3.y, w3.z, w3.w};
#pragma unroll
        for (int o = 0; o < 16; o++) {
            acc[o][0] = fmaf(wv[o], xv.x, acc[o][0]);
            acc[o][1] = fmaf(wv[o], xv.y, acc[o][1]);
            acc[o][2] = fmaf(wv[o], xv.z, acc[o][2]);
            acc[o][3] = fmaf(wv[o], xv.w, acc[o][3]);
        }
    }

    float* yp = y + ((size_t)b * O + o0) * NN + n0;
#pragma unroll
    for (int o = 0; o < 16; o++) {
        float bb = sb[o];
        float4 r = make_float4(acc[o][0] + bb, acc[o][1] + bb,
                               acc[o][2] + bb, acc[o][3] + bb);
        *(float4*)(yp + (size_t)o * NN) = r;
    }
}

// ---------------------------------------------------------------------------
// 2) scores[b, n, m] = sum_{c<32} q[b,c,n] * k[b,c,m]
//    grid: (NN/64, NN/64, BB), block 256 (16x16 threads, 4x4 per thread)
// ---------------------------------------------------------------------------
__global__ void scores_kernel() {
    __shared__ float sq[CQK][64];
    __shared__ float sk[CQK][64];

    const int b  = blockIdx.z;
    const int n0 = blockIdx.y * 64;
    const int m0 = blockIdx.x * 64;
    const int tid = threadIdx.x;

    const float* qb = g_q + (size_t)b * CQK * NN;
    const float* kb = g_k + (size_t)b * CQK * NN;

#pragma unroll
    for (int i = 0; i < 8; i++) {
        int idx = tid + i * 256;
        int c  = idx >> 6;
        int nn = idx & 63;
        sq[c][nn] = qb[(size_t)c * NN + n0 + nn];
        sk[c][nn] = kb[(size_t)c * NN + m0 + nn];
    }
    __syncthreads();

    const int tn = tid >> 4;   // 0..15
    const int tm = tid & 15;   // 0..15
    float acc[4][4];
#pragma unroll
    for (int i = 0; i < 4; i++)
#pragma unroll
        for (int j = 0; j < 4; j++) acc[i][j] = 0.f;

#pragma unroll
    for (int c = 0; c < CQK; c++) {
        float4 qv = *(const float4*)&sq[c][tn * 4];
        float4 kv = *(const float4*)&sk[c][tm * 4];
        float qf[4] = {qv.x, qv.y, qv.z, qv.w};
        float kf[4] = {kv.x, kv.y, kv.z, kv.w};
#pragma unroll
        for (int i = 0; i < 4; i++)
#pragma unroll
            for (int j = 0; j < 4; j++)
                acc[i][j] = fmaf(qf[i], kf[j], acc[i][j]);
    }

#pragma unroll
    for (int i = 0; i < 4; i++) {
        float4 r = make_float4(acc[i][0], acc[i][1], acc[i][2], acc[i][3]);
        *(float4*)&g_s[((size_t)b * NN + n0 + tn * 4 + i) * NN + m0 + tm * 4] = r;
    }
}

// ---------------------------------------------------------------------------
// 3) Row softmax over g_s: one block (256 thr) per row of 4096.
//    Values held in registers between the max and sum passes.
// ---------------------------------------------------------------------------
__global__ void softmax_kernel() {
    __shared__ float red[8];
    const size_t row = blockIdx.x;          // b*NN + n
    float* p = g_s + row * NN;
    const int tid = threadIdx.x;

    float v[16];
    float mx = -3.0e38f;
    float4* p4 = (float4*)p;
#pragma unroll
    for (int i = 0; i < 4; i++) {
        float4 t = p4[tid + i * 256];
        v[i*4+0] = t.x; v[i*4+1] = t.y; v[i*4+2] = t.z; v[i*4+3] = t.w;
        mx = fmaxf(mx, fmaxf(fmaxf(t.x, t.y), fmaxf(t.z, t.w)));
    }
#pragma unroll
    for (int o = 16; o; o >>= 1) mx = fmaxf(mx, __shfl_xor_sync(0xffffffffu, mx, o));
    if ((tid & 31) == 0) red[tid >> 5] = mx;
    __syncthreads();
    float m = red[0];
#pragma unroll
    for (int i = 1; i < 8; i++) m = fmaxf(m, red[i]);

    float sum = 0.f;
#pragma unroll
    for (int i = 0; i < 16; i++) {
        v[i] = expf(v[i] - m);
        sum += v[i];
    }
#pragma unroll
    for (int o = 16; o; o >>= 1) sum += __shfl_xor_sync(0xffffffffu, sum, o);
    __syncthreads();
    if ((tid & 31) == 0) red[tid >> 5] = sum;
    __syncthreads();
    float s = 0.f;
#pragma unroll
    for (int i = 0; i < 8; i++) s += red[i];
    float inv = 1.f / s;

#pragma unroll
    for (int i = 0; i < 4; i++) {
        float4 t = make_float4(v[i*4+0] * inv, v[i*4+1] * inv,
                               v[i*4+2] * inv, v[i*4+3] * inv);
        p4[tid + i * 256] = t;
    }
}

// ---------------------------------------------------------------------------
// 4) out[b,c,n] = x[b,c,n] + sum_m v[b,c,m] * attn[b,n,m]
//    GEMM with both operands K(m)-major. 128x128 tile, KT=16, 8x8 micro-tile,
//    register-prefetch over the K loop. grid: (NN/128, CC/128, BB), block 256.
// ---------------------------------------------------------------------------
__global__ void out_kernel(const float* __restrict__ x, float* __restrict__ out) {
    __shared__ float sV[16][132];   // [m][c], padded
    __shared__ float sA[16][132];   // [m][n], padded

    const int b  = blockIdx.z;
    const int cB = blockIdx.y * 128;
    const int nB = blockIdx.x * 128;
    const int tid = threadIdx.x;

    const float* vb = g_v + ((size_t)b * CC + cB) * NN;
    const float* ab = g_s + ((size_t)b * NN + nB) * NN;

    const int tc = tid >> 4;   // 0..15 -> c micro-row
    const int tn = tid & 15;   // 0..15 -> n micro-col (coalesced stores)

    float4 pv[2], pa[2];

    // addressing for tile loads: idx covers 128 rows x 4 float4 chunks of m
    const int r0  = (tid + 0)   >> 2;
    const int mq0 = ((tid + 0)  & 3) * 4;
    const int r1  = (tid + 256) >> 2;
    const int mq1 = ((tid + 256)& 3) * 4;

    float acc[8][8];
#pragma unroll
    for (int i = 0; i < 8; i++)
#pragma unroll
        for (int j = 0; j < 8; j++) acc[i][j] = 0.f;

    // prefetch tile 0
    pv[0] = *(const float4*)(vb + (size_t)r0 * NN + mq0);
    pa[0] = *(const float4*)(ab + (size_t)r0 * NN + mq0);
    pv[1] = *(const float4*)(vb + (size_t)r1 * NN + mq1);
    pa[1] = *(const float4*)(ab + (size_t)r1 * NN + mq1);
    sV[mq0+0][r0] = pv[0].x; sV[mq0+1][r0] = pv[0].y; sV[mq0+2][r0] = pv[0].z; sV[mq0+3][r0] = pv[0].w;
    sA[mq0+0][r0] = pa[0].x; sA[mq0+1][r0] = pa[0].y; sA[mq0+2][r0] = pa[0].z; sA[mq0+3][r0] = pa[0].w;
    sV[mq1+0][r1] = pv[1].x; sV[mq1+1][r1] = pv[1].y; sV[mq1+2][r1] = pv[1].z; sV[mq1+3][r1] = pv[1].w;
    sA[mq1+0][r1] = pa[1].x; sA[mq1+1][r1] = pa[1].y; sA[mq1+2][r1] = pa[1].z; sA[mq1+3][r1] = pa[1].w;
    __syncthreads();

    const int KT = NN / 16;   // 256 K-iterations
    for (int kt = 0; kt < KT; kt++) {
        if (kt + 1 < KT) {
            int m0 = (kt + 1) * 16;
            pv[0] = *(const float4*)(vb + (size_t)r0 * NN + m0 + mq0);
            pa[0] = *(const float4*)(ab + (size_t)r0 * NN + m0 + mq0);
            pv[1] = *(const float4*)(vb + (size_t)r1 * NN + m0 + mq1);
            pa[1] = *(const float4*)(ab + (size_t)r1 * NN + m0 + mq1);
        }

#pragma unroll
        for (int m = 0; m < 16; m++) {
            float4 v0 = *(const float4*)&sV[m][tc * 8];
            float4 v1 = *(const float4*)&sV[m][tc * 8 + 4];
            float4 a0 = *(const float4*)&sA[m][tn * 8];
            float4 a1 = *(const float4*)&sA[m][tn * 8 + 4];
            float vf[8] = {v0.x, v0.y, v0.z, v0.w, v1.x, v1.y, v1.z, v1.w};
            float af[8] = {a0.x, a0.y, a0.z, a0.w, a1.x, a1.y, a1.z, a1.w};
#pragma unroll
            for (int i = 0; i < 8; i++)
#pragma unroll
                for (int j = 0; j < 8; j++)
                    acc[i][j] = fmaf(vf[i], af[j], acc[i][j]);
        }
        __syncthreads();
        if (kt + 1 < KT) {
            sV[mq0+0][r0] = pv[0].x; sV[mq0+1][r0] = pv[0].y; sV[mq0+2][r0] = pv[0].z; sV[mq0+3][r0] = pv[0].w;
            sA[mq0+0][r0] = pa[0].x; sA[mq0+1][r0] = pa[0].y; sA[mq0+2][r0] = pa[0].z; sA[mq0+3][r0] = pa[0].w;
            sV[mq1+0][r1] = pv[1].x; sV[mq1+1][r1] = pv[1].y; sV[mq1+2][r1] = pv[1].z; sV[mq1+3][r1] = pv[1].w;
            sA[mq1+0][r1] = pa[1].x; sA[mq1+1][r1] = pa[1].y; sA[mq1+2][r1] = pa[1].z; sA[mq1+3][r1] = pa[1].w;
            __syncthreads();
        }
    }

    // epilogue: residual add + store (coalesced: tn contiguous in n)
    const float* xb = x + ((size_t)b * CC + cB) * NN + nB;
    float*       ob = out + ((size_t)b * CC + cB) * NN + nB;
#pragma unroll
    for (int i = 0; i < 8; i++) {
        int c = tc * 8 + i;
#pragma unroll
        for (int j = 0; j < 2; j++) {
            int n = tn * 8 + j * 4;
            float4 xv = *(const float4*)(xb + (size_t)c * NN + n);
            float4 r = make_float4(xv.x + acc[i][j*4+0], xv.y + acc[i][j*4+1],
                                   xv.z + acc[i][j*4+2], xv.w + acc[i][j*4+3]);
            *(float4*)(ob + (size_t)c * NN + n) = r;
        }
    }
}

// ---------------------------------------------------------------------------
extern "C" void kernel_launch(void* const* d_in, const int* in_sizes, int n_in,
                              void* d_out, int out_size) {
    const float* x  = (const float*)d_in[0];
    const float* Wq = (const float*)d_in[1];
    const float* bq = (const float*)d_in[2];
    const float* Wk = (const float*)d_in[3];
    const float* bk = (const float*)d_in[4];
    const float* Wv = (const float*)d_in[5];
    const float* bv = (const float*)d_in[6];
    float* out = (float*)d_out;

    // 1) projections
    proj_kernel<<<dim3(NN / 1024, CQK / 16, BB), 256>>>(x, Wq, bq, 0, CQK);
    proj_kernel<<<dim3(NN / 1024, CQK / 16, BB), 256>>>(x, Wk, bk, 1, CQK);
    proj_kernel<<<dim3(NN / 1024, CC  / 16, BB), 256>>>(x, Wv, bv, 2, CC);

    // 2) scores = q^T k
    scores_kernel<<<dim3(NN / 64, NN / 64, BB), 256>>>();

    // 3) softmax over last dim
    softmax_kernel<<<BB * NN, 256>>>();

    // 4) out = v @ attn^T + x
    out_kernel<<<dim3(NN / 128, CC / 128, BB), 256>>>(x, out);
}

// round 3
// speedup vs baseline: 2.7387x; 2.7387x over previous
#include <cuda_runtime.h>

#define BB  4
#define CC  256
#define CQK 32
#define NN  4096
#define TS  40          // smem tile row stride in words (160B: 16B-aligned, conflict-free v2 loads)

// Scratch (allocation-free: __device__ globals)
// k-dim of MMA operands is stored PERMUTED within each 8-group: [k0,k4,k1,k5,k2,k6,k3,k7]
__device__ float g_qt[BB * NN * CQK];        // [b][n][c-perm], tf32-rounded
__device__ float g_kt[BB * NN * CQK];        // [b][m][c-perm], tf32-rounded
__device__ float g_v [BB * CC * NN];         // [b][c][m-perm], tf32-rounded
__device__ float g_s [(size_t)BB * NN * NN]; // scores: raw fp32 [b][n][m]; after softmax: attn [b][n][m-perm] tf32

// ===========================================================================
// helpers
// ===========================================================================
__device__ __forceinline__ unsigned smem_u32(const void* p) {
    unsigned a;
    asm("{ .reg .u64 t; cvta.to.shared.u64 t, %1; cvt.u32.u64 %0, t; }"
        : "=r"(a) : "l"(p));
    return a;
}
__device__ __forceinline__ float to_tf32(float x) {
    unsigned u;
    asm("cvt.rna.tf32.f32 %0, %1;" : "=r"(u) : "f"(x));
    return __uint_as_float(u);
}
__device__ __forceinline__ void cp16(unsigned dst, const void* src) {
    asm volatile("cp.async.cg.shared.global [%0], [%1], 16;" :: "r"(dst), "l"(src));
}
#define CP_COMMIT()  asm volatile("cp.async.commit_group;")
#define CP_WAIT(n)   asm volatile("cp.async.wait_group %0;" :: "n"(n))

__device__ __forceinline__ void lds2(unsigned addr, unsigned& x, unsigned& y) {
    asm volatile("ld.shared.v2.b32 {%0, %1}, [%2];" : "=r"(x), "=r"(y) : "r"(addr));
}
__device__ __forceinline__ void mma8(float c[4],
                                     unsigned a0, unsigned a1, unsigned a2, unsigned a3,
                                     unsigned b0, unsigned b1) {
    asm volatile(
        "mma.sync.aligned.m16n8k8.row.col.f32.tf32.tf32.f32 "
        "{%0,%1,%2,%3}, {%4,%5,%6,%7}, {%8,%9}, {%0,%1,%2,%3};"
        : "+f"(c[0]), "+f"(c[1]), "+f"(c[2]), "+f"(c[3])
        : "r"(a0), "r"(a1), "r"(a2), "r"(a3), "r"(b0), "r"(b1));
}

// ===========================================================================
// 1) Projection. which: 0 -> g_qt, 1 -> g_kt (transposed + c-permuted),
//    2 -> g_v ([c][m] layout, m-permuted). All outputs tf32-rounded.
//    grid: (NN/1024, O/16, BB), block 256.
// ===========================================================================
__global__ void proj_kernel(const float* __restrict__ x,
                            const float* __restrict__ W,
                            const float* __restrict__ bias,
                            int which, int O) {
    __shared__ float sW[CC][16];
    __shared__ float sb[16];

    const int b   = blockIdx.z;
    const int o0  = blockIdx.y * 16;
    const int tid = threadIdx.x;

#pragma unroll
    for (int i = 0; i < 16; i++) {
        int idx = tid + i * 256;
        int o = idx >> 8;
        int c = idx & 255;
        sW[c][o] = W[(o0 + o) * CC + c];
    }
    if (tid < 16) sb[tid] = bias[o0 + tid];
    __syncthreads();

    const int n0 = blockIdx.x * 1024 + tid * 4;
    float acc[16][4];
#pragma unroll
    for (int o = 0; o < 16; o++)
#pragma unroll
        for (int j = 0; j < 4; j++) acc[o][j] = 0.f;

    const float* xp = x + (size_t)b * CC * NN + n0;

#pragma unroll 4
    for (int c = 0; c < CC; c++) {
        float4 xv = *(const float4*)(xp + (size_t)c * NN);
        float4 w0 = *(const float4*)&sW[c][0];
        float4 w1 = *(const float4*)&sW[c][4];
        float4 w2 = *(const float4*)&sW[c][8];
        float4 w3 = *(const float4*)&sW[c][12];
        float wv[16] = {w0.x, w0.y, w0.z, w0.w, w1.x, w1.y, w1.z, w1.w,
                        w2.x, w2.y, w2.z, w2.w, w3.x, w3.y, w3.z, w3.w};
#pragma unroll
        for (int o = 0; o < 16; o++) {
            acc[o][0] = fmaf(wv[o], xv.x, acc[o][0]);
            acc[o][1] = fmaf(wv[o], xv.y, acc[o][1]);
            acc[o][2] = fmaf(wv[o], xv.z, acc[o][2]);
            acc[o][3] = fmaf(wv[o], xv.w, acc[o][3]);
        }
    }

    if (which <= 1) {
        // transposed write y[b][n][o-perm], o contiguous (32 per row), tf32-rounded
        float* yt = (which == 0) ? g_qt : g_kt;
        float* base = yt + ((size_t)b * NN + n0) * CQK + o0;
#pragma unroll
        for (int j = 0; j < 4; j++) {
            float vv[16];
#pragma unroll
            for (int o = 0; o < 16; o++) vv[o] = to_tf32(acc[o][j] + sb[o]);
            // permute within each 8-group: [0,4,1,5,2,6,3,7]
            float4 f0 = make_float4(vv[0],  vv[4],  vv[1],  vv[5]);
            float4 f1 = make_float4(vv[2],  vv[6],  vv[3],  vv[7]);
            float4 f2 = make_float4(vv[8],  vv[12], vv[9],  vv[13]);
            float4 f3 = make_float4(vv[10], vv[14], vv[11], vv[15]);
            float* bp = base + (size_t)j * CQK;
            *(float4*)(bp + 0)  = f0;
            *(float4*)(bp + 4)  = f1;
            *(float4*)(bp + 8)  = f2;
            *(float4*)(bp + 12) = f3;
        }
    } else {
        // v[c][m] with m permuted within 8-groups; thread covers 4 m, pair
        // (even,odd adjacent threads) covers a full 8-group. tf32-rounded.
        float* yp = g_v + ((size_t)b * O + o0) * NN + n0;
        const bool ev = (tid & 1) == 0;
#pragma unroll
        for (int o = 0; o < 16; o++) {
            float v0 = to_tf32(acc[o][0] + sb[o]);
            float v1 = to_tf32(acc[o][1] + sb[o]);
            float v2 = to_tf32(acc[o][2] + sb[o]);
            float v3 = to_tf32(acc[o][3] + sb[o]);
            float t1 = __shfl_xor_sync(0xffffffffu, ev ? v2 : v0, 1);
            float t2 = __shfl_xor_sync(0xffffffffu, ev ? v3 : v1, 1);
            float4 r = ev ? make_float4(v0, t1, v1, t2)
                          : make_float4(t1, v2, t2, v3);
            *(float4*)(yp + (size_t)o * NN) = r;
        }
    }
}

// ===========================================================================
// 2) scores[b,n,m] = sum_c q.k  — tf32 mma.sync, block 128x128, warp 64x32.
//    grid: (NN/128 m, NN/128 n, BB), block 256. Output raw fp32 (std order).
// ===========================================================================
__global__ __launch_bounds__(256, 2) void scores_mma_kernel() {
    __shared__ float smem[2 * 128 * TS];

    const int b   = blockIdx.z;
    const int n0  = blockIdx.y * 128;
    const int m0  = blockIdx.x * 128;
    const int tid = threadIdx.x;
    const int wid = tid >> 5, lane = tid & 31;
    const int wr = wid >> 2, wc = wid & 3;
    const int r4 = lane >> 2, q = lane & 3;

    const float* qb = g_qt + ((size_t)b * NN + n0) * CQK;
    const float* kb = g_kt + ((size_t)b * NN + m0) * CQK;

    const unsigned sQ = smem_u32(smem);
    const unsigned sK = sQ + 128 * TS * 4;

#pragma unroll
    for (int i = 0; i < 8; i++) {
        int idx  = tid + i * 256;
        int tile = idx >> 10;
        int r    = (idx & 1023) >> 3;
        int p    = idx & 7;
        const float* g = (tile ? kb : qb) + (size_t)r * CQK + p * 4;
        cp16((tile ? sK : sQ) + (unsigned)(r * TS + p * 4) * 4, g);
    }
    CP_COMMIT();
    CP_WAIT(0);
    __syncthreads();

    float acc[4][4][4];
#pragma unroll
    for (int i = 0; i < 4; i++)
#pragma unroll
        for (int j = 0; j < 4; j++)
#pragma unroll
            for (int t = 0; t < 4; t++) acc[i][j][t] = 0.f;

#pragma unroll
    for (int kk = 0; kk < 4; kk++) {
        unsigned a[4][4], bf[4][2];
#pragma unroll
        for (int mt = 0; mt < 4; mt++) {
            unsigned ad = sQ + (unsigned)((wr * 64 + mt * 16 + r4) * TS + kk * 8 + 2 * q) * 4;
            lds2(ad,              a[mt][0], a[mt][2]);
            lds2(ad + 8 * TS * 4, a[mt][1], a[mt][3]);
        }
#pragma unroll
        for (int nt = 0; nt < 4; nt++) {
            unsigned bd = sK + (unsigned)((wc * 32 + nt * 8 + r4) * TS + kk * 8 + 2 * q) * 4;
            lds2(bd, bf[nt][0], bf[nt][1]);
        }
#pragma unroll
        for (int mt = 0; mt < 4; mt++)
#pragma unroll
            for (int nt = 0; nt < 4; nt++)
                mma8(acc[mt][nt], a[mt][0], a[mt][1], a[mt][2], a[mt][3],
                     bf[nt][0], bf[nt][1]);
    }

    float* srow = g_s + ((size_t)b * NN + n0) * NN + m0;
#pragma unroll
    for (int mt = 0; mt < 4; mt++)
#pragma unroll
        for (int nt = 0; nt < 4; nt++) {
            int row = wr * 64 + mt * 16 + r4;
            int col = wc * 32 + nt * 8 + 2 * q;
            *(float2*)(srow + (size_t)row * NN + col) =
                make_float2(acc[mt][nt][0], acc[mt][nt][1]);
            *(float2*)(srow + (size_t)(row + 8) * NN + col) =
                make_float2(acc[mt][nt][2], acc[mt][nt][3]);
        }
}

// ===========================================================================
// 3) Row softmax over g_s; writes attn tf32-rounded with m permuted in 8-groups.
//    One block (256 thr) per row; thread handles two 8-float groups.
// ===========================================================================
__global__ void softmax_kernel() {
    __shared__ float red[8];
    const size_t row = blockIdx.x;
    float4* p4 = (float4*)(g_s + row * NN);
    const int tid = threadIdx.x;

    float v[16];
    float mx = -3.0e38f;
#pragma unroll
    for (int g = 0; g < 2; g++) {
        float4 t0 = p4[2 * tid + g * 512];
        float4 t1 = p4[2 * tid + g * 512 + 1];
        float* vg = v + g * 8;
        vg[0] = t0.x; vg[1] = t0.y; vg[2] = t0.z; vg[3] = t0.w;
        vg[4] = t1.x; vg[5] = t1.y; vg[6] = t1.z; vg[7] = t1.w;
#pragma unroll
        for (int i = 0; i < 8; i++) mx = fmaxf(mx, vg[i]);
    }
#pragma unroll
    for (int o = 16; o; o >>= 1) mx = fmaxf(mx, __shfl_xor_sync(0xffffffffu, mx, o));
    if ((tid & 31) == 0) red[tid >> 5] = mx;
    __syncthreads();
    float m = red[0];
#pragma unroll
    for (int i = 1; i < 8; i++) m = fmaxf(m, red[i]);

    float sum = 0.f;
#pragma unroll
    for (int i = 0; i < 16; i++) {
        v[i] = expf(v[i] - m);
        sum += v[i];
    }
#pragma unroll
    for (int o = 16; o; o >>= 1) sum += __shfl_xor_sync(0xffffffffu, sum, o);
    __syncthreads();
    if ((tid & 31) == 0) red[tid >> 5] = sum;
    __syncthreads();
    float s = 0.f;
#pragma unroll
    for (int i = 0; i < 8; i++) s += red[i];
    float inv = 1.f / s;

#pragma unroll
    for (int g = 0; g < 2; g++) {
        float* vg = v + g * 8;
        float w[8];
#pragma unroll
        for (int i = 0; i < 8; i++) w[i] = to_tf32(vg[i] * inv);
        // permute within 8-group: [0,4,1,5,2,6,3,7]
        p4[2 * tid + g * 512]     = make_float4(w[0], w[4], w[1], w[5]);
        p4[2 * tid + g * 512 + 1] = make_float4(w[2], w[6], w[3], w[7]);
    }
}

// ===========================================================================
// 4) out[b,c,n] = x + sum_m v[b,c,m]*attn[b,n,m] — tf32 mma.sync,
//    block 128c x 128n, warp 64x32, K=4096 in 128 double-buffered cp.async
//    stages of 32. grid: (NN/128, CC/128, BB), block 256, dyn smem 80KB.
// ===========================================================================
__global__ __launch_bounds__(256, 2) void out_mma_kernel(const float* __restrict__ x,
                                                         float* __restrict__ out) {
    extern __shared__ float dsm[];

    const int b   = blockIdx.z;
    const int cB  = blockIdx.y * 128;
    const int nB  = blockIdx.x * 128;
    const int tid = threadIdx.x;
    const int wid = tid >> 5, lane = tid & 31;
    const int wr = wid >> 2, wc = wid & 3;
    const int r4 = lane >> 2, q = lane & 3;

    const float* vb = g_v + ((size_t)b * CC + cB) * NN;
    const float* ab = g_s + ((size_t)b * NN + nB) * NN;

    const unsigned sb0 = smem_u32(dsm);
    const unsigned BUFB = 2u * 128 * TS * 4;      // 40960
    const unsigned TILB = 128u * TS * 4;          // 20480

    // stage issue: V tile then A tile, 8 cp.async per thread
    auto issue = [&](int kt, int buf) {
        const int m0 = kt * 32;
        const unsigned base = sb0 + (unsigned)buf * BUFB;
#pragma unroll
        for (int i = 0; i < 8; i++) {
            int idx  = tid + i * 256;
            int tile = idx >> 10;
            int r    = (idx & 1023) >> 3;
            int p    = idx & 7;
            const float* g = (tile ? ab : vb) + (size_t)r * NN + m0 + p * 4;
            cp16(base + (unsigned)tile * TILB + (unsigned)(r * TS + p * 4) * 4, g);
        }
        CP_COMMIT();
    };

    issue(0, 0);

    float acc[4][4][4];
#pragma unroll
    for (int i = 0; i < 4; i++)
#pragma unroll
        for (int j = 0; j < 4; j++)
#pragma unroll
            for (int t = 0; t < 4; t++) acc[i][j][t] = 0.f;

    const int KT = NN / 32;
    for (int kt = 0; kt < KT; kt++) {
        const int buf = kt & 1;
        if (kt + 1 < KT) { issue(kt + 1, buf ^ 1); CP_WAIT(1); }
        else             { CP_WAIT(0); }
        __syncthreads();

        const unsigned sV = sb0 + (unsigned)buf * BUFB;
        const unsigned sA = sV + TILB;
#pragma unroll
        for (int kk = 0; kk < 4; kk++) {
            unsigned a[4][4], bf[4][2];
#pragma unroll
            for (int mt = 0; mt < 4; mt++) {
                unsigned ad = sV + (unsigned)((wr * 64 + mt * 16 + r4) * TS + kk * 8 + 2 * q) * 4;
                lds2(ad,              a[mt][0], a[mt][2]);
                lds2(ad + 8 * TS * 4, a[mt][1], a[mt][3]);
            }
#pragma unroll
            for (int nt = 0; nt < 4; nt++) {
                unsigned bd = sA + (unsigned)((wc * 32 + nt * 8 + r4) * TS + kk * 8 + 2 * q) * 4;
                lds2(bd, bf[nt][0], bf[nt][1]);
            }
#pragma unroll
            for (int mt = 0; mt < 4; mt++)
#pragma unroll
                for (int nt = 0; nt < 4; nt++)
                    mma8(acc[mt][nt], a[mt][0], a[mt][1], a[mt][2], a[mt][3],
                         bf[nt][0], bf[nt][1]);
        }
        __syncthreads();
    }

    // epilogue: residual add + store (float2 per fragment half)
    const float* xb = x   + ((size_t)b * CC + cB) * NN + nB;
    float*       ob = out + ((size_t)b * CC + cB) * NN + nB;
#pragma unroll
    for (int mt = 0; mt < 4; mt++)
#pragma unroll
        for (int nt = 0; nt < 4; nt++) {
            int row = wr * 64 + mt * 16 + r4;
            int col = wc * 32 + nt * 8 + 2 * q;
            float2 x0 = *(const float2*)(xb + (size_t)row * NN + col);
            float2 x1 = *(const float2*)(xb + (size_t)(row + 8) * NN + col);
            *(float2*)(ob + (size_t)row * NN + col) =
                make_float2(acc[mt][nt][0] + x0.x, acc[mt][nt][1] + x0.y);
            *(float2*)(ob + (size_t)(row + 8) * NN + col) =
                make_float2(acc[mt][nt][2] + x1.x, acc[mt][nt][3] + x1.y);
        }
}

// ===========================================================================
extern "C" void kernel_launch(void* const* d_in, const int* in_sizes, int n_in,
                              void* d_out, int out_size) {
    const float* x  = (const float*)d_in[0];
    const float* Wq = (const float*)d_in[1];
    const float* bq = (const float*)d_in[2];
    const float* Wk = (const float*)d_in[3];
    const float* bk = (const float*)d_in[4];
    const float* Wv = (const float*)d_in[5];
    const float* bv = (const float*)d_in[6];
    float* out = (float*)d_out;

    proj_kernel<<<dim3(NN / 1024, CQK / 16, BB), 256>>>(x, Wq, bq, 0, CQK);
    proj_kernel<<<dim3(NN / 1024, CQK / 16, BB), 256>>>(x, Wk, bk, 1, CQK);
    proj_kernel<<<dim3(NN / 1024, CC  / 16, BB), 256>>>(x, Wv, bv, 2, CC);

    scores_mma_kernel<<<dim3(NN / 128, NN / 128, BB), 256>>>();

    softmax_kernel<<<BB * NN, 256>>>();

    const int dyn_smem = 2 * 2 * 128 * TS * 4;   // 81920
    cudaFuncSetAttribute(out_mma_kernel,
                         cudaFuncAttributeMaxDynamicSharedMemorySize, dyn_smem);
    out_mma_kernel<<<dim3(NN / 128, CC / 128, BB), 256, dyn_smem>>>(x, out);
}

// round 6
// speedup vs baseline: 3.8518x; 1.4064x over previous
#include <cuda_runtime.h>

#define BB  4
#define CC  256
#define CQK 32
#define NN  4096
#define LOG2E 1.4426950408889634f

// q/k: [b][n][c-perm] (c permuted in 8-groups [k0,k4,k1,k5,k2,k6,k3,k7]), tf32.
// q additionally pre-scaled by log2(e).  v: [b][c][m-perm], tf32.
__device__ float g_qt[BB * NN * CQK];
__device__ float g_kt[BB * NN * CQK];
__device__ float g_v [BB * CC * NN];

// smem layout (floats)
#define OFF_Q  0            // 128 x 40
#define OFF_K  5120         // 2 x 64 x 40
#define OFF_V  10240        // 2 x 256 x 72
#define OFF_P  47104        // 128 x 72
#define OFF_SC 56320        // 128
#define OFF_L  56448        // 128
#define SMEM_FLOATS 56576   // 226304 bytes

// ===========================================================================
__device__ __forceinline__ unsigned smem_u32(const void* p) {
    unsigned a;
    asm("{ .reg .u64 t; cvta.to.shared.u64 t, %1; cvt.u32.u64 %0, t; }"
        : "=r"(a) : "l"(p));
    return a;
}
__device__ __forceinline__ float to_tf32(float x) {
    unsigned u;
    asm("cvt.rna.tf32.f32 %0, %1;" : "=r"(u) : "f"(x));
    return __uint_as_float(u);
}
__device__ __forceinline__ float ex2(float x) {
    float y;
    asm("ex2.approx.ftz.f32 %0, %1;" : "=f"(y) : "f"(x));
    return y;
}
__device__ __forceinline__ void cp16(unsigned dst, const void* src) {
    asm volatile("cp.async.cg.shared.global [%0], [%1], 16;" :: "r"(dst), "l"(src));
}
#define CP_COMMIT()  asm volatile("cp.async.commit_group;")
#define CP_WAIT(n)   asm volatile("cp.async.wait_group %0;" :: "n"(n))

__device__ __forceinline__ void lds2(unsigned addr, unsigned& x, unsigned& y) {
    asm volatile("ld.shared.v2.b32 {%0, %1}, [%2];" : "=r"(x), "=r"(y) : "r"(addr));
}
__device__ __forceinline__ void mma8(float c[4],
                                     unsigned a0, unsigned a1, unsigned a2, unsigned a3,
                                     unsigned b0, unsigned b1) {
    asm volatile(
        "mma.sync.aligned.m16n8k8.row.col.f32.tf32.tf32.f32 "
        "{%0,%1,%2,%3}, {%4,%5,%6,%7}, {%8,%9}, {%0,%1,%2,%3};"
        : "+f"(c[0]), "+f"(c[1]), "+f"(c[2]), "+f"(c[3])
        : "r"(a0), "r"(a1), "r"(a2), "r"(a3), "r"(b0), "r"(b1));
}

// ===========================================================================
// 1) Projection (same as R3; q gets log2e fold)
// ===========================================================================
__global__ void proj_kernel(const float* __restrict__ x,
                            const float* __restrict__ W,
                            const float* __restrict__ bias,
                            int which, int O) {
    __shared__ float sW[CC][16];
    __shared__ float sb[16];

    const int b   = blockIdx.z;
    const int o0  = blockIdx.y * 16;
    const int tid = threadIdx.x;

#pragma unroll
    for (int i = 0; i < 16; i++) {
        int idx = tid + i * 256;
        int o = idx >> 8;
        int c = idx & 255;
        sW[c][o] = W[(o0 + o) * CC + c];
    }
    if (tid < 16) sb[tid] = bias[o0 + tid];
    __syncthreads();

    const int n0 = blockIdx.x * 1024 + tid * 4;
    float acc[16][4];
#pragma unroll
    for (int o = 0; o < 16; o++)
#pragma unroll
        for (int j = 0; j < 4; j++) acc[o][j] = 0.f;

    const float* xp = x + (size_t)b * CC * NN + n0;

#pragma unroll 4
    for (int c = 0; c < CC; c++) {
        float4 xv = *(const float4*)(xp + (size_t)c * NN);
        float4 w0 = *(const float4*)&sW[c][0];
        float4 w1 = *(const float4*)&sW[c][4];
        float4 w2 = *(const float4*)&sW[c][8];
        float4 w3 = *(const float4*)&sW[c][12];
        float wv[16] = {w0.x, w0.y, w0.z, w0.w, w1.x, w1.y, w1.z, w1.w,
                        w2.x, w2.y, w2.z, w2.w, w3.x, w3.y, w3.z, w3.w};
#pragma unroll
        for (int o = 0; o < 16; o++) {
            acc[o][0] = fmaf(wv[o], xv.x, acc[o][0]);
            acc[o][1] = fmaf(wv[o], xv.y, acc[o][1]);
            acc[o][2] = fmaf(wv[o], xv.z, acc[o][2]);
            acc[o][3] = fmaf(wv[o], xv.w, acc[o][3]);
        }
    }

    if (which <= 1) {
        const float sc = (which == 0) ? LOG2E : 1.0f;
        float* yt = (which == 0) ? g_qt : g_kt;
        float* base = yt + ((size_t)b * NN + n0) * CQK + o0;
#pragma unroll
        for (int j = 0; j < 4; j++) {
            float vv[16];
#pragma unroll
            for (int o = 0; o < 16; o++) vv[o] = to_tf32((acc[o][j] + sb[o]) * sc);
            float4 f0 = make_float4(vv[0],  vv[4],  vv[1],  vv[5]);
            float4 f1 = make_float4(vv[2],  vv[6],  vv[3],  vv[7]);
            float4 f2 = make_float4(vv[8],  vv[12], vv[9],  vv[13]);
            float4 f3 = make_float4(vv[10], vv[14], vv[11], vv[15]);
            float* bp = base + (size_t)j * CQK;
            *(float4*)(bp + 0)  = f0;
            *(float4*)(bp + 4)  = f1;
            *(float4*)(bp + 8)  = f2;
            *(float4*)(bp + 12) = f3;
        }
    } else {
        float* yp = g_v + ((size_t)b * O + o0) * NN + n0;
        const bool ev = (tid & 1) == 0;
#pragma unroll
        for (int o = 0; o < 16; o++) {
            float v0 = to_tf32(acc[o][0] + sb[o]);
            float v1 = to_tf32(acc[o][1] + sb[o]);
            float v2 = to_tf32(acc[o][2] + sb[o]);
            float v3 = to_tf32(acc[o][3] + sb[o]);
            float t1 = __shfl_xor_sync(0xffffffffu, ev ? v2 : v0, 1);
            float t2 = __shfl_xor_sync(0xffffffffu, ev ? v3 : v1, 1);
            float4 r = ev ? make_float4(v0, t1, v1, t2)
                          : make_float4(t1, v2, t2, v3);
            *(float4*)(yp + (size_t)o * NN) = r;
        }
    }
}

// ===========================================================================
// 2) Flash attention: per block (b, 128-row n-tile), loop m-tiles of 64.
//    scores MMA (warp=16 rows x 64 m) -> online softmax (in-warp) -> P smem
//    -> out MMA (warps 2n x 4c, acc 128n x 256c in regs) -> /l, +x, store.
// ===========================================================================
__global__ __launch_bounds__(256, 1) void flash_kernel(const float* __restrict__ x,
                                                       float* __restrict__ out) {
    extern __shared__ float sm[];

    const int b   = blockIdx.y;
    const int n0  = blockIdx.x * 128;
    const int tid = threadIdx.x;
    const int wid = tid >> 5, lane = tid & 31;
    const int r4 = lane >> 2, q = lane & 3;
    const int wr = wid >> 2, wc = wid & 3;

    const unsigned sb  = smem_u32(sm);
    const unsigned sQ  = sb + OFF_Q * 4;
    const unsigned sK  = sb + OFF_K * 4;
    const unsigned sV  = sb + OFF_V * 4;
    const unsigned sP  = sb + OFF_P * 4;
    float* fP  = sm + OFF_P;
    float* fSC = sm + OFF_SC;
    float* fL  = sm + OFF_L;

    const float* qg = g_qt + ((size_t)b * NN + n0) * CQK;
    const float* kg0 = g_kt + (size_t)b * NN * CQK;
    const float* vg0 = g_v  + (size_t)b * CC * NN;

    // ---- prologue: q tile + first K/V tiles via cp.async
#pragma unroll
    for (int i = 0; i < 4; i++) {
        int idx = tid + i * 256;
        int row = idx >> 3, p = idx & 7;
        cp16(sQ + (unsigned)(row * 40 + p * 4) * 4, qg + (size_t)row * CQK + p * 4);
    }
    {
#pragma unroll
        for (int i = 0; i < 2; i++) {
            int idx = tid + i * 256;
            int row = idx >> 3, p = idx & 7;
            cp16(sK + (unsigned)(row * 40 + p * 4) * 4, kg0 + (size_t)row * CQK + p * 4);
        }
#pragma unroll
        for (int i = 0; i < 16; i++) {
            int idx = tid + i * 256;
            int row = idx >> 4, p = idx & 15;
            cp16(sV + (unsigned)(row * 72 + p * 4) * 4, vg0 + (size_t)row * NN + p * 4);
        }
    }
    CP_COMMIT();
    CP_WAIT(0);
    __syncthreads();

    // q fragments (whole kernel): warp owns rows 16*wid..+15
    const int rowS = 16 * wid + r4;
    unsigned qf[4][4];
#pragma unroll
    for (int kk = 0; kk < 4; kk++) {
        unsigned ad = sQ + (unsigned)(rowS * 40 + kk * 8 + 2 * q) * 4;
        lds2(ad,             qf[kk][0], qf[kk][2]);
        lds2(ad + 8 * 40 * 4, qf[kk][1], qf[kk][3]);
    }

    float acc[4][8][4];
#pragma unroll
    for (int mt = 0; mt < 4; mt++)
#pragma unroll
        for (int nt = 0; nt < 8; nt++)
#pragma unroll
            for (int j = 0; j < 4; j++) acc[mt][nt][j] = 0.f;

    float mA = -1e30f, mB = -1e30f, lA = 0.f, lB = 0.f;

    const int STEPS = NN / 64;
    for (int s = 0; s < STEPS; s++) {
        if (s > 0) CP_WAIT(0);
        __syncthreads();   // K/V buf(s) visible; P(s-1) fully consumed

        if (s + 1 < STEPS) {
            const int m1 = (s + 1) * 64;
            const unsigned kd = sK + (unsigned)((s + 1) & 1) * (64 * 40 * 4);
            const float* kg = kg0 + (size_t)m1 * CQK;
#pragma unroll
            for (int i = 0; i < 2; i++) {
                int idx = tid + i * 256;
                int row = idx >> 3, p = idx & 7;
                cp16(kd + (unsigned)(row * 40 + p * 4) * 4, kg + (size_t)row * CQK + p * 4);
            }
            const unsigned vd = sV + (unsigned)((s + 1) & 1) * (256 * 72 * 4);
#pragma unroll
            for (int i = 0; i < 16; i++) {
                int idx = tid + i * 256;
                int row = idx >> 4, p = idx & 15;
                cp16(vd + (unsigned)(row * 72 + p * 4) * 4,
                     vg0 + (size_t)row * NN + m1 + p * 4);
            }
            CP_COMMIT();
        }

        // ---- scores: 16 rows x 64 m per warp
        const unsigned kbuf = sK + (unsigned)(s & 1) * (64 * 40 * 4);
        float sacc[8][4];
#pragma unroll
        for (int nt = 0; nt < 8; nt++)
#pragma unroll
            for (int j = 0; j < 4; j++) sacc[nt][j] = 0.f;

#pragma unroll
        for (int kk = 0; kk < 4; kk++) {
            unsigned kb[8][2];
#pragma unroll
            for (int nt = 0; nt < 8; nt++)
                lds2(kbuf + (unsigned)((nt * 8 + r4) * 40 + kk * 8 + 2 * q) * 4,
                     kb[nt][0], kb[nt][1]);
#pragma unroll
            for (int nt = 0; nt < 8; nt++)
                mma8(sacc[nt], qf[kk][0], qf[kk][1], qf[kk][2], qf[kk][3],
                     kb[nt][0], kb[nt][1]);
        }

        // ---- online softmax stats (base-2; log2e folded into q)
        float rmA = sacc[0][0], rmB = sacc[0][2];
#pragma unroll
        for (int nt = 0; nt < 8; nt++) {
            rmA = fmaxf(rmA, fmaxf(sacc[nt][0], sacc[nt][1]));
            rmB = fmaxf(rmB, fmaxf(sacc[nt][2], sacc[nt][3]));
        }
#pragma unroll
        for (int off = 1; off <= 2; off <<= 1) {
            rmA = fmaxf(rmA, __shfl_xor_sync(0xffffffffu, rmA, off));
            rmB = fmaxf(rmB, __shfl_xor_sync(0xffffffffu, rmB, off));
        }
        const float mnA = fmaxf(mA, rmA), mnB = fmaxf(mB, rmB);
        const float scA = ex2(mA - mnA),  scB = ex2(mB - mnB);
        mA = mnA; mB = mnB;

        float lsA = 0.f, lsB = 0.f;
#pragma unroll
        for (int nt = 0; nt < 8; nt++) {
            float p0 = to_tf32(ex2(sacc[nt][0] - mnA));
            float p1 = to_tf32(ex2(sacc[nt][1] - mnA));
            float p2 = to_tf32(ex2(sacc[nt][2] - mnB));
            float p3 = to_tf32(ex2(sacc[nt][3] - mnB));
            sacc[nt][0] = p0; sacc[nt][1] = p1; sacc[nt][2] = p2; sacc[nt][3] = p3;
            lsA += p0 + p1; lsB += p2 + p3;
        }
#pragma unroll
        for (int off = 1; off <= 2; off <<= 1) {
            lsA += __shfl_xor_sync(0xffffffffu, lsA, off);
            lsB += __shfl_xor_sync(0xffffffffu, lsB, off);
        }
        lA = lA * scA + lsA;
        lB = lB * scB + lsB;

        // ---- P -> smem (k-permuted cols for v2 operand loads)
#pragma unroll
        for (int nt = 0; nt < 8; nt++) {
#pragma unroll
            for (int j = 0; j < 4; j++) {
                int k = 2 * q + (j & 1);
                int pos = 2 * (k & 3) + (k >> 2);
                int row = rowS + 8 * (j >> 1);
                fP[row * 72 + nt * 8 + pos] = sacc[nt][j];
            }
        }
        if (q == 0) { fSC[rowS] = scA; fSC[rowS + 8] = scB; }
        __syncthreads();

        // ---- rescale out accumulator (vote-skip when max unchanged)
        float scr[8];
#pragma unroll
        for (int mt = 0; mt < 4; mt++) {
            scr[2 * mt]     = fSC[wr * 64 + mt * 16 + r4];
            scr[2 * mt + 1] = fSC[wr * 64 + mt * 16 + r4 + 8];
        }
        bool ones = true;
#pragma unroll
        for (int k = 0; k < 8; k++) ones = ones && (scr[k] == 1.0f);
        if (!__all_sync(0xffffffffu, ones)) {
#pragma unroll
            for (int mt = 0; mt < 4; mt++)
#pragma unroll
                for (int nt = 0; nt < 8; nt++) {
                    acc[mt][nt][0] *= scr[2 * mt];
                    acc[mt][nt][1] *= scr[2 * mt];
                    acc[mt][nt][2] *= scr[2 * mt + 1];
                    acc[mt][nt][3] *= scr[2 * mt + 1];
                }
        }

        // ---- out MMA: acc[n 64(wr) x c 64(wc)] += P @ V^T over m=64
        const unsigned vbuf = sV + (unsigned)(s & 1) * (256 * 72 * 4);
#pragma unroll
        for (int kk = 0; kk < 8; kk++) {
            unsigned af[4][4], bf[8][2];
#pragma unroll
            for (int mt = 0; mt < 4; mt++) {
                unsigned ad = sP + (unsigned)((wr * 64 + mt * 16 + r4) * 72 + kk * 8 + 2 * q) * 4;
                lds2(ad,             af[mt][0], af[mt][2]);
                lds2(ad + 8 * 72 * 4, af[mt][1], af[mt][3]);
            }
#pragma unroll
            for (int nt = 0; nt < 8; nt++)
                lds2(vbuf + (unsigned)((wc * 64 + nt * 8 + r4) * 72 + kk * 8 + 2 * q) * 4,
                     bf[nt][0], bf[nt][1]);
#pragma unroll
            for (int mt = 0; mt < 4; mt++)
#pragma unroll
                for (int nt = 0; nt < 8; nt++)
                    mma8(acc[mt][nt], af[mt][0], af[mt][1], af[mt][2], af[mt][3],
                         bf[nt][0], bf[nt][1]);
        }
    }

    // ---- finalize: /l
    if (q == 0) { fL[rowS] = lA; fL[rowS + 8] = lB; }
    __syncthreads();
    float linv[8];
#pragma unroll
    for (int mt = 0; mt < 4; mt++) {
        linv[2 * mt]     = 1.f / fL[wr * 64 + mt * 16 + r4];
        linv[2 * mt + 1] = 1.f / fL[wr * 64 + mt * 16 + r4 + 8];
    }
#pragma unroll
    for (int mt = 0; mt < 4; mt++)
#pragma unroll
        for (int nt = 0; nt < 8; nt++) {
            acc[mt][nt][0] *= linv[2 * mt];
            acc[mt][nt][1] *= linv[2 * mt];
            acc[mt][nt][2] *= linv[2 * mt + 1];
            acc[mt][nt][3] *= linv[2 * mt + 1];
        }

    // ---- epilogue: transpose n x c -> c x n via smem (reuse V area), +x, store
    float* fT = sm + OFF_V;   // 128 x 132
    const float* xb = x   + (size_t)b * CC * NN + n0;
    float*       ob = out + (size_t)b * CC * NN + n0;
#pragma unroll 1
    for (int ch = 0; ch < 2; ch++) {
        __syncthreads();
        if ((wc >> 1) == ch) {
#pragma unroll
            for (int mt = 0; mt < 4; mt++)
#pragma unroll
                for (int nt = 0; nt < 8; nt++)
#pragma unroll
                    for (int j = 0; j < 4; j++) {
                        int cl = (wc & 1) * 64 + nt * 8 + 2 * q + (j & 1);
                        int rn = wr * 64 + mt * 16 + r4 + 8 * (j >> 1);
                        fT[cl * 132 + rn] = acc[mt][nt][j];
                    }
        }
        __syncthreads();
#pragma unroll
        for (int i = 0; i < 16; i++) {
            int idx = tid + i * 256;
            int cr = idx >> 5;
            int n4 = (idx & 31) * 4;
            float4 t = *(const float4*)&fT[cr * 132 + n4];
            const size_t go = (size_t)(ch * 128 + cr) * NN + n4;
            float4 xv = *(const float4*)(xb + go);
            *(float4*)(ob + go) = make_float4(t.x + xv.x, t.y + xv.y,
                                              t.z + xv.z, t.w + xv.w);
        }
    }
}

// ===========================================================================
extern "C" void kernel_launch(void* const* d_in, const int* in_sizes, int n_in,
                              void* d_out, int out_size) {
    const float* x  = (const float*)d_in[0];
    const float* Wq = (const float*)d_in[1];
    const float* bq = (const float*)d_in[2];
    const float* Wk = (const float*)d_in[3];
    const float* bk = (const float*)d_in[4];
    const float* Wv = (const float*)d_in[5];
    const float* bv = (const float*)d_in[6];
    float* out = (float*)d_out;

    proj_kernel<<<dim3(NN / 1024, CQK / 16, BB), 256>>>(x, Wq, bq, 0, CQK);
    proj_kernel<<<dim3(NN / 1024, CQK / 16, BB), 256>>>(x, Wk, bk, 1, CQK);
    proj_kernel<<<dim3(NN / 1024, CC  / 16, BB), 256>>>(x, Wv, bv, 2, CC);

    const int dyn = SMEM_FLOATS * 4;   // 226304 B
    cudaFuncSetAttribute(flash_kernel,
                         cudaFuncAttributeMaxDynamicSharedMemorySize, dyn);
    flash_kernel<<<dim3(NN / 128, BB), 256, dyn>>>(x, out);
}